// round 10
// baseline (speedup 1.0000x reference)
#include <cuda_runtime.h>

// Problem constants
#define B_ 8
#define C_ 256
#define N_ 16384
#define K_ 128

// Decomposition: CTA = (batch, 64-channel slice, 1-of-9 N interleave)
#define SLICE_C 64
#define NSLICE 4                // C_/SLICE_C
#define NS 9                    // N interleave -> 8*4*9 = 288 CTAs, 2/SM
#define TN 64                   // points per chunk
#define TPB 512
#define NCHUNKS (N_ / TN)       // 256 chunks, round-robin over NS
#define TROW 68                 // padded smem row stride (floats/uints)
#define TAB_U (K_ * TROW)       // smem table uints
#define TABC (K_ * SLICE_C)     // 8192 compact cells per group-slice
#define NGROUP (B_ * NSLICE)    // 32 groups

// Shared global max-table: 32 groups x 8192 cells = 1 MB. Zero-initialized;
// the convert kernel resets it after reading (graph-replay deterministic).
__device__ unsigned int g_table[NGROUP * TABC];

// Monotone float -> uint key: unsigned order == float order.
__device__ __forceinline__ unsigned int fkey(float f) {
    int i = __float_as_int(f);
    return (i >= 0) ? ((unsigned int)i | 0x80000000u) : ~(unsigned int)i;
}
__device__ __forceinline__ float funkey(unsigned int k) {
    unsigned int i = (k & 0x80000000u) ? (k & 0x7FFFFFFFu) : ~k;
    return __int_as_float((int)i);
}

// Phase 1: fused transpose + per-CTA segment-max, 2-deep reg pipeline, 2 CTAs/SM.
__global__ __launch_bounds__(TPB, 2)
void seg_phase1(const float* __restrict__ pf, const int* __restrict__ cids,
                float* __restrict__ out_pf) {
    extern __shared__ unsigned int smem[];
    unsigned int* tab = smem;                          // [K][TROW], 34.8 KB
    float* tile = (float*)(smem + TAB_U);              // [TN][TROW] point-major
    int* scid = (int*)(tile + TN * TROW);              // TN ids

    const int tid = threadIdx.x;
    const int b = blockIdx.y;
    const int cslice = blockIdx.x / NS;                // 0..3
    const int ns = blockIdx.x - cslice * NS;           // 0..8

    {   // init smem table
        uint4 z = make_uint4(0u, 0u, 0u, 0u);
        uint4* t4 = (uint4*)tab;
        #pragma unroll
        for (int i = tid; i < TAB_U / 4; i += TPB) t4[i] = z;
    }

    const float* src = pf + (size_t)b * C_ * N_ + (size_t)cslice * SLICE_C * N_;
    const int* cidp = cids + b * N_;

    // chunk count: 256 = 9*28 + 4 -> ns<4 get 29, else 28
    const int cnt = (NCHUNKS / NS) + (ns < (NCHUNKS % NS) ? 1 : 0);

    // Loader: thread owns point ln, channel quads cg4 and cg4+32 (in-slice)
    const int ln = tid & 63;
    const int cg4 = (tid >> 6) * 4;     // 0,4,...,28
    // Consumer: 4 consecutive channels per thread; warp = 2 points
    const int c4 = (tid & 15) * 4;      // 0..60
    const int pb = tid >> 4;            // 0..31

    auto prefetch = [&](int i, float* rr, int& cidr) {
        const int m = ns + NS * i;
        const float* p0 = src + (size_t)cg4 * N_ + m * TN + ln;
        #pragma unroll
        for (int j = 0; j < 4; j++) {
            rr[j]     = __ldcs(p0 + (size_t)j * N_);
            rr[4 + j] = __ldcs(p0 + (size_t)(32 + j) * N_);
        }
        if (tid < TN) cidr = cidp[m * TN + tid];
    };

    float rA[8], rB[8];
    int cidA = 0, cidB = 0;
    prefetch(0, rA, cidA);
    if (cnt > 1) prefetch(1, rB, cidB);

    auto body = [&](int i, float* rr, int& cidr) {
        __syncthreads();                               // prev tile fully consumed
        *(float4*)(tile + ln * TROW + cg4)      = make_float4(rr[0], rr[1], rr[2], rr[3]);
        *(float4*)(tile + ln * TROW + cg4 + 32) = make_float4(rr[4], rr[5], rr[6], rr[7]);
        if (tid < TN) scid[tid] = cidr;
        __syncthreads();                               // tile + scid ready

        if (i + 2 < cnt) prefetch(i + 2, rr, cidr);    // refill freed buffer

        const int n0 = (ns + NS * i) * TN;
        #pragma unroll
        for (int q = 0; q < 2; q++) {
            const int p = pb + q * 32;
            float4 vv = *(const float4*)(tile + p * TROW + c4);
            __stcs((float4*)(out_pf + ((size_t)b * N_ + n0 + p) * C_
                             + cslice * SLICE_C + c4), vv);
            const int cid = scid[p];
            if (cid >= 0) {
                unsigned int* cell = &tab[cid * TROW + c4];
                uint4 cur = *(const uint4*)cell;       // LDS.128 filter read
                unsigned int k0 = fkey(vv.x); if (cur.x < k0) atomicMax(cell + 0, k0);
                unsigned int k1 = fkey(vv.y); if (cur.y < k1) atomicMax(cell + 1, k1);
                unsigned int k2 = fkey(vv.z); if (cur.z < k2) atomicMax(cell + 2, k2);
                unsigned int k3 = fkey(vv.w); if (cur.w < k3) atomicMax(cell + 3, k3);
            }
        }
    };

    int i = 0;
    #pragma unroll 1
    for (; i + 1 < cnt; i += 2) {
        body(i,     rA, cidA);
        body(i + 1, rB, cidB);
    }
    if (i < cnt) body(i, rA, cidA);                    // odd tail
    __syncthreads();

    // merge smem table into the shared global table via REDG atomicMax
    unsigned int* gt = g_table + (size_t)(b * NSLICE + cslice) * TABC;
    #pragma unroll
    for (int j = tid; j < TABC; j += TPB) {
        int row = j >> 6;
        int col = j & 63;
        atomicMax(gt + j, tab[row * TROW + col]);      // no return -> REDG
    }
}

// Convert: g_table keys -> out_seg floats (sentinel->0), and reset table to 0.
__global__ void seg_convert(float* __restrict__ out_seg) {
    int g = blockIdx.x * blockDim.x + threadIdx.x;     // 0 .. NGROUP*TABC/4-1
    // decode (b, slice, k, c16) from table-linear order
    int b = g >> 13;                                   // / (NSLICE*K*16)
    int r = g & 8191;
    int slice = r >> 11;                               // / (K*16)
    int r2 = r & 2047;
    int k = r2 >> 4;
    int c4 = (r2 & 15) * 4;
    uint4* t = (uint4*)g_table + g;
    uint4 mx = *t;
    *t = make_uint4(0u, 0u, 0u, 0u);                   // reset for next replay
    float4 o;
    o.x = mx.x ? funkey(mx.x) : 0.0f;
    o.y = mx.y ? funkey(mx.y) : 0.0f;
    o.z = mx.z ? funkey(mx.z) : 0.0f;
    o.w = mx.w ? funkey(mx.w) : 0.0f;
    ((float4*)out_seg)[(((size_t)b * K_ + k) * C_ + slice * SLICE_C + c4) >> 2] = o;
}

extern "C" void kernel_launch(void* const* d_in, const int* in_sizes, int n_in,
                              void* d_out, int out_size) {
    const float* pf = (const float*)d_in[0];      // (B,C,N) f32
    const int* cid  = (const int*)d_in[1];        // (B,N) i32
    float* out      = (float*)d_out;
    float* out_seg  = out;                        // (B*K, C)
    float* out_pf   = out + (size_t)B_ * K_ * C_; // (B*N, C)

    const size_t smem_bytes = (size_t)TAB_U * 4 + (size_t)TN * TROW * 4 + (size_t)TN * 4;
    cudaFuncSetAttribute(seg_phase1, cudaFuncAttributeMaxDynamicSharedMemorySize,
                         (int)smem_bytes);

    dim3 grid(NSLICE * NS, B_);                   // 36 x 8 = 288 CTAs, 2/SM
    seg_phase1<<<grid, TPB, smem_bytes>>>(pf, cid, out_pf);

    const int t2 = NGROUP * TABC / 4;             // 65536 threads
    seg_convert<<<t2 / 256, 256>>>(out_seg);
}

// round 11
// speedup vs baseline: 1.3484x; 1.3484x over previous
#include <cuda_runtime.h>

// Problem constants
#define B_ 8
#define C_ 256
#define N_ 16384
#define K_ 128

// Decomposition: CTA = (batch, 64-channel slice, 1-of-9 N interleave)
#define SLICE_C 64
#define NSLICE 4                // C_/SLICE_C
#define NS 9                    // N interleave -> 8*4*9 = 288 CTAs, 2/SM
#define TN 64                   // points per chunk
#define TPB 512
#define NCHUNKS (N_ / TN)       // 256 chunks, round-robin over NS
#define TROW 68                 // padded row stride (floats/uints)
#define TAB_U (K_ * TROW)       // 8704 uints per-CTA table

// Per-CTA partial tables: 288 x 34.8KB ~= 10 MB.
__device__ unsigned int g_scratch[B_ * NSLICE * NS * TAB_U];

// Monotone float -> uint key: unsigned order == float order.
__device__ __forceinline__ unsigned int fkey(float f) {
    int i = __float_as_int(f);
    return (i >= 0) ? ((unsigned int)i | 0x80000000u) : ~(unsigned int)i;
}
__device__ __forceinline__ float funkey(unsigned int k) {
    unsigned int i = (k & 0x80000000u) ? (k & 0x7FFFFFFFu) : ~k;
    return __int_as_float((int)i);
}

// Branch-free conditional shared max: SETP + @p RED.SHARED (no BSSY/BSYNC).
// key==0 (or key<=cur) => predicate off => no-op.
__device__ __forceinline__ void smax_if(unsigned int* cell, unsigned int cur,
                                        unsigned int key) {
    unsigned int addr = (unsigned int)__cvta_generic_to_shared(cell);
    asm volatile(
        "{\n\t.reg .pred p;\n\t"
        "setp.lt.u32 p, %1, %2;\n\t"
        "@p red.shared.max.u32 [%0], %2;\n\t}"
        :: "r"(addr), "r"(cur), "r"(key) : "memory");
}

// Phase 1: fused transpose + per-CTA segment-max, 2-deep reg pipeline, 2 CTAs/SM.
__global__ __launch_bounds__(TPB, 2)
void seg_phase1(const float* __restrict__ pf, const int* __restrict__ cids,
                float* __restrict__ out_pf) {
    extern __shared__ unsigned int smem[];
    unsigned int* tab = smem;                          // [K][TROW], 34.8 KB
    float* tile = (float*)(smem + TAB_U);              // [TN][TROW] point-major
    int* scid = (int*)(tile + TN * TROW);              // TN ids

    const int tid = threadIdx.x;
    const int b = blockIdx.y;
    const int cslice = blockIdx.x / NS;                // 0..3
    const int ns = blockIdx.x - cslice * NS;           // 0..8

    {   // init table
        uint4 z = make_uint4(0u, 0u, 0u, 0u);
        uint4* t4 = (uint4*)tab;
        #pragma unroll
        for (int i = tid; i < TAB_U / 4; i += TPB) t4[i] = z;
    }

    const float* src = pf + (size_t)b * C_ * N_ + (size_t)cslice * SLICE_C * N_;
    const int* cidp = cids + b * N_;

    // chunk count for this ns: 256 = 9*28 + 4 -> ns<4 get 29, else 28
    const int cnt = (NCHUNKS / NS) + (ns < (NCHUNKS % NS) ? 1 : 0);

    // Loader: thread owns point ln, channel quads cg4 and cg4+32 (in-slice)
    const int ln = tid & 63;
    const int cg4 = (tid >> 6) * 4;     // 0,4,...,28
    // Consumer: 4 consecutive channels per thread; warp = 2 points
    const int c4 = (tid & 15) * 4;      // 0..60
    const int pb = tid >> 4;            // 0..31

    auto prefetch = [&](int i, float* rr, int& cidr) {
        const int m = ns + NS * i;
        const float* p0 = src + (size_t)cg4 * N_ + m * TN + ln;
        #pragma unroll
        for (int j = 0; j < 4; j++) {
            rr[j]     = __ldcs(p0 + (size_t)j * N_);
            rr[4 + j] = __ldcs(p0 + (size_t)(32 + j) * N_);
        }
        if (tid < TN) cidr = cidp[m * TN + tid];
    };

    float rA[8], rB[8];
    int cidA = 0, cidB = 0;
    prefetch(0, rA, cidA);
    if (cnt > 1) prefetch(1, rB, cidB);

    auto body = [&](int i, float* rr, int& cidr) {
        __syncthreads();                               // prev tile fully consumed
        *(float4*)(tile + ln * TROW + cg4)      = make_float4(rr[0], rr[1], rr[2], rr[3]);
        *(float4*)(tile + ln * TROW + cg4 + 32) = make_float4(rr[4], rr[5], rr[6], rr[7]);
        if (tid < TN) scid[tid] = cidr;
        __syncthreads();                               // tile + scid ready

        if (i + 2 < cnt) prefetch(i + 2, rr, cidr);    // refill freed buffer

        const int n0 = (ns + NS * i) * TN;
        #pragma unroll
        for (int q = 0; q < 2; q++) {
            const int p = pb + q * 32;
            float4 vv = *(const float4*)(tile + p * TROW + c4);
            __stcs((float4*)(out_pf + ((size_t)b * N_ + n0 + p) * C_
                             + cslice * SLICE_C + c4), vv);
            const int cid = scid[p];
            const int en = (cid >= 0);
            unsigned int* cell = &tab[(en ? cid : 0) * TROW + c4];
            uint4 cur = *(const uint4*)cell;           // LDS.128 filter read
            // key forced to 0 when disabled -> predicate always off
            unsigned int k0 = en ? fkey(vv.x) : 0u;
            unsigned int k1 = en ? fkey(vv.y) : 0u;
            unsigned int k2 = en ? fkey(vv.z) : 0u;
            unsigned int k3 = en ? fkey(vv.w) : 0u;
            smax_if(cell + 0, cur.x, k0);
            smax_if(cell + 1, cur.y, k1);
            smax_if(cell + 2, cur.z, k2);
            smax_if(cell + 3, cur.w, k3);
        }
    };

    int i = 0;
    #pragma unroll 1
    for (; i + 1 < cnt; i += 2) {
        body(i,     rA, cidA);
        body(i + 1, rB, cidB);
    }
    if (i < cnt) body(i, rA, cidA);                    // odd tail
    __syncthreads();

    // dump table (plain stores)
    uint4* dst = (uint4*)(g_scratch
                 + (size_t)((b * NSLICE + cslice) * NS + ns) * TAB_U);
    const uint4* t4 = (const uint4*)tab;
    #pragma unroll
    for (int i2 = tid; i2 < TAB_U / 4; i2 += TPB) dst[i2] = t4[i2];
}

// Phase 2: reduce NS=9 partials per output float4 (one thread per quad).
__global__ void seg_phase2(float* __restrict__ out_seg) {
    int g = blockIdx.x * blockDim.x + threadIdx.x;     // 0 .. B*K*C/4-1
    const int PER_B = K_ * C_ / 4;                     // 8192
    int b = g / PER_B;
    int rem = g - b * PER_B;
    int k = rem >> 6;
    int cg = rem & 63;
    int c = cg * 4;
    int slice = c >> 6;
    int cc = c & 63;
    const unsigned int* base = g_scratch
        + (size_t)((b * NSLICE + slice) * NS) * TAB_U + k * TROW + cc;
    uint4 mx = make_uint4(0u, 0u, 0u, 0u);
    #pragma unroll
    for (int s = 0; s < NS; s++) {
        uint4 v = *(const uint4*)(base + (size_t)s * TAB_U);
        mx.x = max(mx.x, v.x); mx.y = max(mx.y, v.y);
        mx.z = max(mx.z, v.z); mx.w = max(mx.w, v.w);
    }
    float4 o;
    o.x = mx.x ? funkey(mx.x) : 0.0f;
    o.y = mx.y ? funkey(mx.y) : 0.0f;
    o.z = mx.z ? funkey(mx.z) : 0.0f;
    o.w = mx.w ? funkey(mx.w) : 0.0f;
    ((float4*)out_seg)[g] = o;
}

extern "C" void kernel_launch(void* const* d_in, const int* in_sizes, int n_in,
                              void* d_out, int out_size) {
    const float* pf = (const float*)d_in[0];      // (B,C,N) f32
    const int* cid  = (const int*)d_in[1];        // (B,N) i32
    float* out      = (float*)d_out;
    float* out_seg  = out;                        // (B*K, C)
    float* out_pf   = out + (size_t)B_ * K_ * C_; // (B*N, C)

    const size_t smem_bytes = (size_t)TAB_U * 4 + (size_t)TN * TROW * 4 + (size_t)TN * 4;
    cudaFuncSetAttribute(seg_phase1, cudaFuncAttributeMaxDynamicSharedMemorySize,
                         (int)smem_bytes);

    dim3 grid(NSLICE * NS, B_);                   // 36 x 8 = 288 CTAs, 2/SM
    seg_phase1<<<grid, TPB, smem_bytes>>>(pf, cid, out_pf);

    const int t2 = B_ * K_ * C_ / 4;              // 65536
    seg_phase2<<<t2 / 256, 256>>>(out_seg);
}